// round 16
// baseline (speedup 1.0000x reference)
#include <cuda_runtime.h>

// spu(z) = z^2 - 0.5 (z>=0), sigmoid(-z) - 1 (z<0); dspu analogous.
// Elementwise over d = 16,777,216 fp32; 192 MiB in + 192 MiB out -> HBM stream.
// R15 = champion (R5/R12/R14: 56.3us kernel / 61.9us bench, DRAM 78%) with ONE
// change: write-through stores (__stwt / st.global.wt). Stores are never read
// back; .wt avoids L2 write-allocate + deferred write-back, freeing LTS
// capacity/sectors for the read stream. Loads stay default-cached.

__device__ __forceinline__ float tanh_half(float z) {
    float t;
    asm("tanh.approx.f32 %0, %1;" : "=f"(t) : "f"(0.5f * z));
    return t;
}

// spu(z) with one MUFU: t = tanh(z/2); negative branch = -0.5 - 0.5*t
__device__ __forceinline__ float spu_f(float z) {
    float t = tanh_half(z);
    float neg = fmaf(-0.5f, t, -0.5f);       // sigmoid(-z) - 1
    float pos = fmaf(z, z, -0.5f);
    return (z >= 0.0f) ? pos : neg;
}

__device__ __forceinline__ void spu_elem(float x, float l, float u,
                                         float& xo, float& lo, float& uo) {
    // p = clip(u - (|l|+|u|)/2, l, u)
    float p = u - 0.5f * (fabsf(l) + fabsf(u));
    p = fminf(fmaxf(p, l), u);

    float sl = spu_f(l);
    float su = spu_f(u);

    // tangent at p, one tanh shared by sp and dspu(p):
    //   sp  (p<0) = -0.5 - 0.5*t
    //   dspu(p<0) = 0.25*t^2 - 0.25
    float tp = tanh_half(p);
    bool  ppos = (p >= 0.0f);
    float sp        = ppos ? fmaf(p, p, -0.5f) : fmaf(-0.5f, tp, -0.5f);
    float tan_slope = ppos ? (2.0f * p)        : fmaf(0.25f * tp, tp, -0.25f);
    float tan_int   = sp - p * tan_slope;

    // chord through (l, sl), (u, su)
    float du = (u != l) ? (u - l) : 1.0f;
    float chord_slope = __fdividef(su - sl, du);
    float chord_int   = sl - chord_slope * l;

    // line through (l, sl) and (0, -0.5)
    float dl = (l != 0.0f) ? (-l) : 1.0f;
    float zl_slope = __fdividef(-0.5f - sl, dl);

    bool upos = (u > 0.0f);

    float lb_slope = upos ? (ppos ? tan_slope : zl_slope) : chord_slope;
    float lb_int   = upos ? (ppos ? tan_int   : -0.5f   ) : chord_int;
    float ub_slope = upos ? chord_slope : tan_slope;
    float ub_int   = upos ? chord_int   : tan_int;

    lo = fmaf((lb_slope > 0.0f) ? l : u, lb_slope, lb_int);
    uo = fmaf((ub_slope > 0.0f) ? u : l, ub_slope, ub_int);
    xo = spu_f(x);
}

__global__ __launch_bounds__(256)
void spu_transformer_kernel(const float4* __restrict__ x,
                            const float4* __restrict__ l,
                            const float4* __restrict__ u,
                            float4* __restrict__ x_out,
                            float4* __restrict__ l_out,
                            float4* __restrict__ u_out,
                            int n4) {
    int i = blockIdx.x * blockDim.x + threadIdx.x;
    if (i >= n4) return;

    float4 xv = x[i];
    float4 lv = l[i];
    float4 uv = u[i];

    float4 xo, lo, uo;
    spu_elem(xv.x, lv.x, uv.x, xo.x, lo.x, uo.x);
    spu_elem(xv.y, lv.y, uv.y, xo.y, lo.y, uo.y);
    spu_elem(xv.z, lv.z, uv.z, xo.z, lo.z, uo.z);
    spu_elem(xv.w, lv.w, uv.w, xo.w, lo.w, uo.w);

    __stwt(x_out + i, xo);
    __stwt(l_out + i, lo);
    __stwt(u_out + i, uo);
}

extern "C" void kernel_launch(void* const* d_in, const int* in_sizes, int n_in,
                              void* d_out, int out_size) {
    const float* x = (const float*)d_in[0];
    const float* l = (const float*)d_in[1];
    const float* u = (const float*)d_in[2];
    float* out = (float*)d_out;

    int n = in_sizes[0];            // 16,777,216
    int n4 = n >> 2;                // divisible by 4

    float* x_out = out;
    float* l_out = out + (size_t)n;
    float* u_out = out + 2 * (size_t)n;

    int threads = 256;
    int blocks = (n4 + threads - 1) / threads;   // 16384
    spu_transformer_kernel<<<blocks, threads>>>(
        (const float4*)x, (const float4*)l, (const float4*)u,
        (float4*)x_out, (float4*)l_out, (float4*)u_out, n4);
}